// round 13
// baseline (speedup 1.0000x reference)
#include <cuda_runtime.h>
#include <cstdint>

// AR(3), 2 dims, diagonal alpha. 4096 trials x 8192 steps.
// One block per trial, 4 tiles of 2048 noise steps, SEG=16, dims fused.
// Producer/consumer split: threads 128-255 own all cp.async traffic (two
// half-tile commit groups per tile); threads 0-127 run B/scan/prefix/C as
// pure compute. Warp-chain is replicated across scan threads (no serial
// section, no S3 barrier): 3 barriers per tile.
//   B: 16 x LDS.64: zero-init dual-chain run -> 6-float offset b
//   scan: uniform-matrix affine scan (shuffle b only; per-dim A^(16*2^k))
//   prefix: each scan thread composes warp-prefix + replicated carry
//   C: re-run both chains from true states, in-place
//   D: coalesced float2 flush -> out (all 256 threads)
// Tail zero-filled via cp.async src-size=0 -> branchless fixed loops.

#define TRIALS 4096
#define STEPS  8192
#define NNOISE (STEPS - 3)     // 8189
#define TILE   2048
#define NTILES 4               // 3 x 2048 + 2045 (zero-padded)
#define SEG    16
#define NSEG   128
#define NTH    256
#define PITCH  17              // float2 per segment (16 + 1 pad): word stride 34
#define BUFSZ  (NSEG * PITCH)  // 2176 float2 per buffer

__device__ __forceinline__ void cp_async8(uint32_t dst, const void* src, int sz) {
    asm volatile("cp.async.ca.shared.global [%0], [%1], 8, %2;"
                 :: "r"(dst), "l"(src), "r"(sz));
}
// smem byte offset of pair s within a buffer
__device__ __forceinline__ uint32_t pair_off(int s) {
    return (uint32_t)((((s >> 4) * PITCH + (s & 15)) << 3));
}

__global__ __launch_bounds__(NTH, 5)
void arma_scan(const float* __restrict__ alpha, const float* __restrict__ xmu,
               const float* __restrict__ sigma, const float* __restrict__ rho_p,
               const float* __restrict__ mu,    const float* __restrict__ x_0,
               const float* __restrict__ normals, float* __restrict__ out)
{
    __shared__ float2 smv[2 * BUFSZ];        // 2 x 17408 B = 34.8 KB
    __shared__ float  swL[2][6][9];          // per-dim A^(16*2^k), k=0..5
    __shared__ float  swb[4][6];             // warp-total offsets

    const int tid  = threadIdx.x;
    const int lane = tid & 31;
    const int wd   = tid >> 5;
    const int tr   = blockIdx.x;
    const bool producer = (tid >= 128);
    const int  pt  = tid & 127;              // producer index / scan index

    // ---- parameters ----
    const float s0v = sigma[0], s1v = sigma[1];
    const float rho = rho_p[0];
    const float c10 = rho * s1v;
    const float c11 = sqrtf(1.0f - rho * rho) * s1v;
    const float k0  = mu[0] + xmu[0] * (1.0f - alpha[0] - alpha[2] - alpha[4]);
    const float k1  = mu[1] + xmu[1] * (1.0f - alpha[1] - alpha[3] - alpha[5]);
    const float p0 = alpha[0], p1 = alpha[2], p2 = alpha[4];   // dim 0
    const float q0 = alpha[1], q1 = alpha[3], q2 = alpha[5];   // dim 1

    const float2* nsrc = (const float2*)normals + (size_t)tr * NNOISE;
    float2*       odst = (float2*)out + (size_t)tr * STEPS;
    const uint32_t sbase = (uint32_t)__cvta_generic_to_shared(smv);

    // first ORDER outputs = x_0 verbatim
    if (tid < 6) out[(size_t)tr * STEPS * 2 + tid] = x_0[tr * 6 + tid];

    // ---- one-time: level matrices A^(16*2^k) for dim = tid (threads 0,1) ----
    if (tid < 2) {
        const float a0 = alpha[0 + tid], a1 = alpha[2 + tid], a2 = alpha[4 + tid];
        float m0=1,m1=0,m2=0, m3=0,m4=1,m5=0, m6=0,m7=0,m8=1;
        #pragma unroll
        for (int j = 0; j < SEG; ++j) {
            float r0 = fmaf(a0, m0, fmaf(a1, m3, a2 * m6));
            float r1 = fmaf(a0, m1, fmaf(a1, m4, a2 * m7));
            float r2 = fmaf(a0, m2, fmaf(a1, m5, a2 * m8));
            m0=m3; m1=m4; m2=m5;  m3=m6; m4=m7; m5=m8;  m6=r0; m7=r1; m8=r2;
        }
        float* L = swL[tid][0];
        L[0]=m0; L[1]=m1; L[2]=m2; L[3]=m3; L[4]=m4; L[5]=m5; L[6]=m6; L[7]=m7; L[8]=m8;
        #pragma unroll
        for (int k = 1; k < 6; ++k) {
            float c0 = fmaf(m0,m0, fmaf(m1,m3, m2*m6));
            float c1 = fmaf(m0,m1, fmaf(m1,m4, m2*m7));
            float c2 = fmaf(m0,m2, fmaf(m1,m5, m2*m8));
            float c3 = fmaf(m3,m0, fmaf(m4,m3, m5*m6));
            float c4 = fmaf(m3,m1, fmaf(m4,m4, m5*m7));
            float c5 = fmaf(m3,m2, fmaf(m4,m5, m5*m8));
            float c6 = fmaf(m6,m0, fmaf(m7,m3, m8*m6));
            float c7 = fmaf(m6,m1, fmaf(m7,m4, m8*m7));
            float c8 = fmaf(m6,m2, fmaf(m7,m5, m8*m8));
            m0=c0; m1=c1; m2=c2; m3=c3; m4=c4; m5=c5; m6=c6; m7=c7; m8=c8;
            float* Lk = swL[tid][k];
            Lk[0]=m0; Lk[1]=m1; Lk[2]=m2; Lk[3]=m3; Lk[4]=m4;
            Lk[5]=m5; Lk[6]=m6; Lk[7]=m7; Lk[8]=m8;
        }
    }

    // replicated carry on scan threads (identical values on all 128)
    float cs0=0.f, cs1=0.f, cs2=0.f, cs3=0.f, cs4=0.f, cs5=0.f;
    if (!producer) {
        cs0 = x_0[tr*6 + 0]; cs1 = x_0[tr*6 + 2]; cs2 = x_0[tr*6 + 4];  // d0
        cs3 = x_0[tr*6 + 1]; cs4 = x_0[tr*6 + 3]; cs5 = x_0[tr*6 + 5];  // d1
    }

    // ---- preload tile 0 (producers only; full tile, no tail) ----
    if (producer) {
        #pragma unroll
        for (int k = 0; k < 16; ++k) {
            const int s = pt + k * 128;
            cp_async8(sbase + pair_off(s), nsrc + s, 8);
        }
    }
    asm volatile("cp.async.commit_group;");

    #pragma unroll
    for (int h = 0; h < NTILES; ++h) {
        const int tbase = h * TILE;
        float2* buf = smv + (h & 1) * BUFSZ;

        asm volatile("cp.async.wait_group 0;");
        __syncthreads();                      // S1: tile h resident

        // ---- producers: first half of tile h+1 ----
        if (h + 1 < NTILES) {
            const int gbase = (h + 1) * TILE;
            const uint32_t dbase = sbase + (uint32_t)(((h + 1) & 1) * BUFSZ * 8);
            if (producer) {
                if (h + 1 < NTILES - 1) {
                    #pragma unroll
                    for (int k = 0; k < 8; ++k) {
                        const int s = pt + k * 128;            // [0,1024)
                        cp_async8(dbase + pair_off(s), nsrc + gbase + s, 8);
                    }
                } else {
                    const int nh = NNOISE - gbase;             // 2045
                    #pragma unroll
                    for (int k = 0; k < 8; ++k) {
                        const int s = pt + k * 128;
                        const bool ok = s < nh;
                        cp_async8(dbase + pair_off(s),
                                  ok ? (nsrc + gbase + s) : nsrc, ok ? 8 : 0);
                    }
                }
            }
        }
        asm volatile("cp.async.commit_group;");

        // ---- phase B (scan threads): zero-init dual-chain run ----
        float b0=0.f,b1=0.f,b2=0.f, b3=0.f,b4=0.f,b5=0.f;
        if (!producer) {
            const float2* np = buf + pt * PITCH;
            #pragma unroll
            for (int j = 0; j < SEG; ++j) {
                float2 rn = np[j];
                float e0 = fmaf(s0v, rn.x, k0);
                float e1 = fmaf(c10, rn.x, fmaf(c11, rn.y, k1));
                float x = fmaf(p2, b2, fmaf(p1, b1, fmaf(p0, b0, e0)));
                float y = fmaf(q2, b5, fmaf(q1, b4, fmaf(q0, b3, e1)));
                b0 = b1; b1 = b2; b2 = x;
                b3 = b4; b4 = b5; b5 = y;
            }

            // ---- uniform-matrix inclusive b-scan ----
            #pragma unroll
            for (int k = 0; k < 5; ++k) {
                const int sh = 1 << k;
                float pb0 = __shfl_up_sync(0xffffffffu, b0, sh);
                float pb1 = __shfl_up_sync(0xffffffffu, b1, sh);
                float pb2 = __shfl_up_sync(0xffffffffu, b2, sh);
                float pb3 = __shfl_up_sync(0xffffffffu, b3, sh);
                float pb4 = __shfl_up_sync(0xffffffffu, b4, sh);
                float pb5 = __shfl_up_sync(0xffffffffu, b5, sh);
                if (lane >= sh) {
                    const float* L0 = swL[0][k];
                    const float* L1 = swL[1][k];
                    b0 = fmaf(L0[0], pb0, fmaf(L0[1], pb1, fmaf(L0[2], pb2, b0)));
                    b1 = fmaf(L0[3], pb0, fmaf(L0[4], pb1, fmaf(L0[5], pb2, b1)));
                    b2 = fmaf(L0[6], pb0, fmaf(L0[7], pb1, fmaf(L0[8], pb2, b2)));
                    b3 = fmaf(L1[0], pb3, fmaf(L1[1], pb4, fmaf(L1[2], pb5, b3)));
                    b4 = fmaf(L1[3], pb3, fmaf(L1[4], pb4, fmaf(L1[5], pb5, b4)));
                    b5 = fmaf(L1[6], pb3, fmaf(L1[7], pb4, fmaf(L1[8], pb5, b5)));
                }
            }
            if (lane == 31) {
                float* bw = swb[wd];
                bw[0]=b0; bw[1]=b1; bw[2]=b2; bw[3]=b3; bw[4]=b4; bw[5]=b5;
            }
        }
        __syncthreads();                      // S2: swb visible

        // ---- producers: second half of tile h+1 ----
        if (h + 1 < NTILES) {
            const int gbase = (h + 1) * TILE;
            const uint32_t dbase = sbase + (uint32_t)(((h + 1) & 1) * BUFSZ * 8);
            if (producer) {
                if (h + 1 < NTILES - 1) {
                    #pragma unroll
                    for (int k = 8; k < 16; ++k) {
                        const int s = pt + k * 128;            // [1024,2048)
                        cp_async8(dbase + pair_off(s), nsrc + gbase + s, 8);
                    }
                } else {
                    const int nh = NNOISE - gbase;
                    #pragma unroll
                    for (int k = 8; k < 16; ++k) {
                        const int s = pt + k * 128;
                        const bool ok = s < nh;
                        cp_async8(dbase + pair_off(s),
                                  ok ? (nsrc + gbase + s) : nsrc, ok ? 8 : 0);
                    }
                }
            }
        }
        asm volatile("cp.async.commit_group;");

        if (!producer) {
            const float* L50 = swL[0][5];
            const float* L51 = swL[1][5];

            // ---- replicated warp-prefix (uses OLD carry) ----
            float t0=cs0,t1=cs1,t2=cs2, t3=cs3,t4=cs4,t5=cs5;
            #pragma unroll
            for (int w = 0; w < 3; ++w) {
                if (wd > w) {
                    const float* bw = swb[w];
                    float u0 = fmaf(L50[0],t0, fmaf(L50[1],t1, fmaf(L50[2],t2, bw[0])));
                    float u1 = fmaf(L50[3],t0, fmaf(L50[4],t1, fmaf(L50[5],t2, bw[1])));
                    float u2 = fmaf(L50[6],t0, fmaf(L50[7],t1, fmaf(L50[8],t2, bw[2])));
                    float u3 = fmaf(L51[0],t3, fmaf(L51[1],t4, fmaf(L51[2],t5, bw[3])));
                    float u4 = fmaf(L51[3],t3, fmaf(L51[4],t4, fmaf(L51[5],t5, bw[4])));
                    float u5 = fmaf(L51[6],t3, fmaf(L51[7],t4, fmaf(L51[8],t5, bw[5])));
                    t0=u0; t1=u1; t2=u2; t3=u3; t4=u4; t5=u5;
                }
            }
            // ---- replicated carry update (identical op order everywhere) ----
            #pragma unroll
            for (int w = 0; w < 4; ++w) {
                const float* bw = swb[w];
                float u0 = fmaf(L50[0],cs0, fmaf(L50[1],cs1, fmaf(L50[2],cs2, bw[0])));
                float u1 = fmaf(L50[3],cs0, fmaf(L50[4],cs1, fmaf(L50[5],cs2, bw[1])));
                float u2 = fmaf(L50[6],cs0, fmaf(L50[7],cs1, fmaf(L50[8],cs2, bw[2])));
                float u3 = fmaf(L51[0],cs3, fmaf(L51[1],cs4, fmaf(L51[2],cs5, bw[3])));
                float u4 = fmaf(L51[3],cs3, fmaf(L51[4],cs4, fmaf(L51[5],cs5, bw[4])));
                float u5 = fmaf(L51[6],cs3, fmaf(L51[7],cs4, fmaf(L51[8],cs5, bw[5])));
                cs0=u0; cs1=u1; cs2=u2; cs3=u3; cs4=u4; cs5=u5;
            }

            // ---- per-lane start: A^(16*lane)*t + exclusive b ----
            float v0=t0,v1=t1,v2=t2, v3=t3,v4=t4,v5=t5;
            #pragma unroll
            for (int k = 0; k < 5; ++k) {
                if (lane & (1 << k)) {
                    const float* L0 = swL[0][k];
                    const float* L1 = swL[1][k];
                    float u0 = fmaf(L0[0],v0, fmaf(L0[1],v1, L0[2]*v2));
                    float u1 = fmaf(L0[3],v0, fmaf(L0[4],v1, L0[5]*v2));
                    float u2 = fmaf(L0[6],v0, fmaf(L0[7],v1, L0[8]*v2));
                    float u3 = fmaf(L1[0],v3, fmaf(L1[1],v4, L1[2]*v5));
                    float u4 = fmaf(L1[3],v3, fmaf(L1[4],v4, L1[5]*v5));
                    float u5 = fmaf(L1[6],v3, fmaf(L1[7],v4, L1[8]*v5));
                    v0=u0; v1=u1; v2=u2; v3=u3; v4=u4; v5=u5;
                }
            }
            float pb0 = __shfl_up_sync(0xffffffffu, b0, 1);
            float pb1 = __shfl_up_sync(0xffffffffu, b1, 1);
            float pb2 = __shfl_up_sync(0xffffffffu, b2, 1);
            float pb3 = __shfl_up_sync(0xffffffffu, b3, 1);
            float pb4 = __shfl_up_sync(0xffffffffu, b4, 1);
            float pb5 = __shfl_up_sync(0xffffffffu, b5, 1);
            float s0 = lane ? (v0 + pb0) : v0;
            float s1 = lane ? (v1 + pb1) : v1;
            float s2 = lane ? (v2 + pb2) : v2;
            float s3 = lane ? (v3 + pb3) : v3;
            float s4 = lane ? (v4 + pb4) : v4;
            float s5 = lane ? (v5 + pb5) : v5;

            // ---- phase C: re-run from true state; overwrite raw with x ----
            float2* wp = buf + pt * PITCH;
            #pragma unroll
            for (int j = 0; j < SEG; ++j) {
                float2 rn = wp[j];
                float e0 = fmaf(s0v, rn.x, k0);
                float e1 = fmaf(c10, rn.x, fmaf(c11, rn.y, k1));
                float x = fmaf(p2, s2, fmaf(p1, s1, fmaf(p0, s0, e0)));
                float y = fmaf(q2, s5, fmaf(q1, s4, fmaf(q0, s3, e1)));
                wp[j] = make_float2(x, y);
                s0 = s1; s1 = s2; s2 = x;
                s3 = s4; s4 = s5; s5 = y;
            }
        }
        __syncthreads();                      // S3 (was S4)

        // ---- phase D: coalesced float2 flush -> out (all 256 threads) ----
        if (h < NTILES - 1) {
            #pragma unroll
            for (int k = 0; k < TILE / NTH; ++k) {
                const int s = tid + k * NTH;
                odst[tbase + 3 + s] = buf[(s >> 4) * PITCH + (s & 15)];
            }
        } else {
            const int nh = NNOISE - tbase;
            #pragma unroll
            for (int k = 0; k < TILE / NTH; ++k) {
                const int s = tid + k * NTH;
                if (s < nh)
                    odst[tbase + 3 + s] = buf[(s >> 4) * PITCH + (s & 15)];
            }
        }
        // no trailing barrier: next iteration's S1 separates D from buffer reuse
    }
}

extern "C" void kernel_launch(void* const* d_in, const int* in_sizes, int n_in,
                              void* d_out, int out_size)
{
    const float* alpha   = (const float*)d_in[0];
    const float* xmu     = (const float*)d_in[1];
    const float* sigma   = (const float*)d_in[2];
    const float* rho     = (const float*)d_in[3];
    const float* mu      = (const float*)d_in[4];
    const float* x_0     = (const float*)d_in[5];
    const float* normals = (const float*)d_in[6];
    float* out = (float*)d_out;

    arma_scan<<<TRIALS, NTH>>>(alpha, xmu, sigma, rho, mu, x_0, normals, out);
}

// round 14
// speedup vs baseline: 1.0683x; 1.0683x over previous
#include <cuda_runtime.h>
#include <cstdint>

// AR(3), 2 dims, diagonal alpha. 4096 trials x 8192 steps.
// One block per trial, 4 tiles of 2048 noise steps, SEG=16, dims fused.
// Double-buffered cp.async pipeline exactly as R11 (all 256 threads issue
// the full next tile right after S1). Warp-total chain is replicated across
// scan threads (no serialized tid0 section, no extra barrier): 3 barriers
// per tile.
//   B: 16 x LDS.64: zero-init dual-chain run -> 6-float offset b
//   scan: uniform-matrix affine scan (shuffle b only; per-dim A^(16*2^k))
//   prefix: each scan thread composes warp-prefix + replicated carry
//   C: re-run both chains from true states, in-place
//   D: coalesced float2 flush -> out (all 256 threads)
// Tail zero-filled via cp.async src-size=0 -> branchless fixed loops.

#define TRIALS 4096
#define STEPS  8192
#define NNOISE (STEPS - 3)     // 8189
#define TILE   2048
#define NTILES 4               // 3 x 2048 + 2045 (zero-padded)
#define SEG    16
#define NSEG   128
#define NTH    256
#define PITCH  17              // float2 per segment (16 + 1 pad): word stride 34
#define BUFSZ  (NSEG * PITCH)  // 2176 float2 per buffer

__device__ __forceinline__ void cp_async8(uint32_t dst, const void* src, int sz) {
    asm volatile("cp.async.ca.shared.global [%0], [%1], 8, %2;"
                 :: "r"(dst), "l"(src), "r"(sz));
}

__global__ __launch_bounds__(NTH, 5)
void arma_scan(const float* __restrict__ alpha, const float* __restrict__ xmu,
               const float* __restrict__ sigma, const float* __restrict__ rho_p,
               const float* __restrict__ mu,    const float* __restrict__ x_0,
               const float* __restrict__ normals, float* __restrict__ out)
{
    __shared__ float2 smv[2 * BUFSZ];        // 2 x 17408 B = 34.8 KB
    __shared__ float  swL[2][6][9];          // per-dim A^(16*2^k), k=0..5
    __shared__ float  swb[4][6];             // warp-total offsets

    const int tid  = threadIdx.x;
    const int lane = tid & 31;
    const int wd   = tid >> 5;
    const int tr   = blockIdx.x;

    // ---- parameters ----
    const float s0v = sigma[0], s1v = sigma[1];
    const float rho = rho_p[0];
    const float c10 = rho * s1v;
    const float c11 = sqrtf(1.0f - rho * rho) * s1v;
    const float k0  = mu[0] + xmu[0] * (1.0f - alpha[0] - alpha[2] - alpha[4]);
    const float k1  = mu[1] + xmu[1] * (1.0f - alpha[1] - alpha[3] - alpha[5]);
    const float p0 = alpha[0], p1 = alpha[2], p2 = alpha[4];   // dim 0
    const float q0 = alpha[1], q1 = alpha[3], q2 = alpha[5];   // dim 1

    const float2* nsrc = (const float2*)normals + (size_t)tr * NNOISE;
    float2*       odst = (float2*)out + (size_t)tr * STEPS;
    const uint32_t sbase = (uint32_t)__cvta_generic_to_shared(smv);

    // first ORDER outputs = x_0 verbatim
    if (tid < 6) out[(size_t)tr * STEPS * 2 + tid] = x_0[tr * 6 + tid];

    // ---- one-time: level matrices A^(16*2^k) for dim = tid (threads 0,1) ----
    if (tid < 2) {
        const float a0 = alpha[0 + tid], a1 = alpha[2 + tid], a2 = alpha[4 + tid];
        float m0=1,m1=0,m2=0, m3=0,m4=1,m5=0, m6=0,m7=0,m8=1;
        #pragma unroll
        for (int j = 0; j < SEG; ++j) {
            float r0 = fmaf(a0, m0, fmaf(a1, m3, a2 * m6));
            float r1 = fmaf(a0, m1, fmaf(a1, m4, a2 * m7));
            float r2 = fmaf(a0, m2, fmaf(a1, m5, a2 * m8));
            m0=m3; m1=m4; m2=m5;  m3=m6; m4=m7; m5=m8;  m6=r0; m7=r1; m8=r2;
        }
        float* L = swL[tid][0];
        L[0]=m0; L[1]=m1; L[2]=m2; L[3]=m3; L[4]=m4; L[5]=m5; L[6]=m6; L[7]=m7; L[8]=m8;
        #pragma unroll
        for (int k = 1; k < 6; ++k) {
            float c0 = fmaf(m0,m0, fmaf(m1,m3, m2*m6));
            float c1 = fmaf(m0,m1, fmaf(m1,m4, m2*m7));
            float c2 = fmaf(m0,m2, fmaf(m1,m5, m2*m8));
            float c3 = fmaf(m3,m0, fmaf(m4,m3, m5*m6));
            float c4 = fmaf(m3,m1, fmaf(m4,m4, m5*m7));
            float c5 = fmaf(m3,m2, fmaf(m4,m5, m5*m8));
            float c6 = fmaf(m6,m0, fmaf(m7,m3, m8*m6));
            float c7 = fmaf(m6,m1, fmaf(m7,m4, m8*m7));
            float c8 = fmaf(m6,m2, fmaf(m7,m5, m8*m8));
            m0=c0; m1=c1; m2=c2; m3=c3; m4=c4; m5=c5; m6=c6; m7=c7; m8=c8;
            float* Lk = swL[tid][k];
            Lk[0]=m0; Lk[1]=m1; Lk[2]=m2; Lk[3]=m3; Lk[4]=m4;
            Lk[5]=m5; Lk[6]=m6; Lk[7]=m7; Lk[8]=m8;
        }
    }

    // replicated carry on scan threads (identical values on all 128)
    float cs0=0.f, cs1=0.f, cs2=0.f, cs3=0.f, cs4=0.f, cs5=0.f;
    if (tid < 128) {
        cs0 = x_0[tr*6 + 0]; cs1 = x_0[tr*6 + 2]; cs2 = x_0[tr*6 + 4];  // d0
        cs3 = x_0[tr*6 + 1]; cs4 = x_0[tr*6 + 3]; cs5 = x_0[tr*6 + 5];  // d1
    }

    // ---- preload tile 0 (full, no tail; all 256 threads) ----
    {
        #pragma unroll
        for (int k = 0; k < TILE / NTH; ++k) {
            const int s = tid + k * NTH;
            cp_async8(sbase + (uint32_t)(((s >> 4) * PITCH + (s & 15)) * 8),
                      nsrc + s, 8);
        }
        asm volatile("cp.async.commit_group;");
    }

    #pragma unroll
    for (int h = 0; h < NTILES; ++h) {
        const int tbase = h * TILE;
        float2* buf = smv + (h & 1) * BUFSZ;

        asm volatile("cp.async.wait_group 0;");
        __syncthreads();                      // S1: tile h resident for all

        // ---- issue next tile's async copy (all 256 threads, full tile) ----
        if (h + 1 < NTILES) {
            const int gbase = (h + 1) * TILE;
            const uint32_t dbase = sbase + (uint32_t)(((h + 1) & 1) * BUFSZ * 8);
            if (h + 1 < NTILES - 1) {
                #pragma unroll
                for (int k = 0; k < TILE / NTH; ++k) {
                    const int s = tid + k * NTH;
                    cp_async8(dbase + (uint32_t)(((s >> 4) * PITCH + (s & 15)) * 8),
                              nsrc + gbase + s, 8);
                }
            } else {
                const int nh = NNOISE - gbase;            // 2045
                #pragma unroll
                for (int k = 0; k < TILE / NTH; ++k) {
                    const int s = tid + k * NTH;
                    const bool ok = s < nh;
                    cp_async8(dbase + (uint32_t)(((s >> 4) * PITCH + (s & 15)) * 8),
                              ok ? (nsrc + gbase + s) : nsrc, ok ? 8 : 0);
                }
            }
            asm volatile("cp.async.commit_group;");
        }

        // ---- phase B: zero-init dual-chain run on raw noise ----
        float b0=0.f,b1=0.f,b2=0.f, b3=0.f,b4=0.f,b5=0.f;
        if (tid < 128) {
            const float2* np = buf + tid * PITCH;
            #pragma unroll
            for (int j = 0; j < SEG; ++j) {
                float2 rn = np[j];
                float e0 = fmaf(s0v, rn.x, k0);
                float e1 = fmaf(c10, rn.x, fmaf(c11, rn.y, k1));
                float x = fmaf(p2, b2, fmaf(p1, b1, fmaf(p0, b0, e0)));
                float y = fmaf(q2, b5, fmaf(q1, b4, fmaf(q0, b3, e1)));
                b0 = b1; b1 = b2; b2 = x;
                b3 = b4; b4 = b5; b5 = y;
            }

            // ---- uniform-matrix inclusive b-scan ----
            #pragma unroll
            for (int k = 0; k < 5; ++k) {
                const int sh = 1 << k;
                float pb0 = __shfl_up_sync(0xffffffffu, b0, sh);
                float pb1 = __shfl_up_sync(0xffffffffu, b1, sh);
                float pb2 = __shfl_up_sync(0xffffffffu, b2, sh);
                float pb3 = __shfl_up_sync(0xffffffffu, b3, sh);
                float pb4 = __shfl_up_sync(0xffffffffu, b4, sh);
                float pb5 = __shfl_up_sync(0xffffffffu, b5, sh);
                if (lane >= sh) {
                    const float* L0 = swL[0][k];
                    const float* L1 = swL[1][k];
                    b0 = fmaf(L0[0], pb0, fmaf(L0[1], pb1, fmaf(L0[2], pb2, b0)));
                    b1 = fmaf(L0[3], pb0, fmaf(L0[4], pb1, fmaf(L0[5], pb2, b1)));
                    b2 = fmaf(L0[6], pb0, fmaf(L0[7], pb1, fmaf(L0[8], pb2, b2)));
                    b3 = fmaf(L1[0], pb3, fmaf(L1[1], pb4, fmaf(L1[2], pb5, b3)));
                    b4 = fmaf(L1[3], pb3, fmaf(L1[4], pb4, fmaf(L1[5], pb5, b4)));
                    b5 = fmaf(L1[6], pb3, fmaf(L1[7], pb4, fmaf(L1[8], pb5, b5)));
                }
            }
            if (lane == 31) {
                float* bw = swb[wd];
                bw[0]=b0; bw[1]=b1; bw[2]=b2; bw[3]=b3; bw[4]=b4; bw[5]=b5;
            }
        }
        __syncthreads();                      // S2: swb visible

        if (tid < 128) {
            const float* L50 = swL[0][5];
            const float* L51 = swL[1][5];

            // ---- replicated warp-prefix (uses OLD carry) ----
            float t0=cs0,t1=cs1,t2=cs2, t3=cs3,t4=cs4,t5=cs5;
            #pragma unroll
            for (int w = 0; w < 3; ++w) {
                if (wd > w) {
                    const float* bw = swb[w];
                    float u0 = fmaf(L50[0],t0, fmaf(L50[1],t1, fmaf(L50[2],t2, bw[0])));
                    float u1 = fmaf(L50[3],t0, fmaf(L50[4],t1, fmaf(L50[5],t2, bw[1])));
                    float u2 = fmaf(L50[6],t0, fmaf(L50[7],t1, fmaf(L50[8],t2, bw[2])));
                    float u3 = fmaf(L51[0],t3, fmaf(L51[1],t4, fmaf(L51[2],t5, bw[3])));
                    float u4 = fmaf(L51[3],t3, fmaf(L51[4],t4, fmaf(L51[5],t5, bw[4])));
                    float u5 = fmaf(L51[6],t3, fmaf(L51[7],t4, fmaf(L51[8],t5, bw[5])));
                    t0=u0; t1=u1; t2=u2; t3=u3; t4=u4; t5=u5;
                }
            }
            // ---- replicated carry update (identical op order everywhere) ----
            #pragma unroll
            for (int w = 0; w < 4; ++w) {
                const float* bw = swb[w];
                float u0 = fmaf(L50[0],cs0, fmaf(L50[1],cs1, fmaf(L50[2],cs2, bw[0])));
                float u1 = fmaf(L50[3],cs0, fmaf(L50[4],cs1, fmaf(L50[5],cs2, bw[1])));
                float u2 = fmaf(L50[6],cs0, fmaf(L50[7],cs1, fmaf(L50[8],cs2, bw[2])));
                float u3 = fmaf(L51[0],cs3, fmaf(L51[1],cs4, fmaf(L51[2],cs5, bw[3])));
                float u4 = fmaf(L51[3],cs3, fmaf(L51[4],cs4, fmaf(L51[5],cs5, bw[4])));
                float u5 = fmaf(L51[6],cs3, fmaf(L51[7],cs4, fmaf(L51[8],cs5, bw[5])));
                cs0=u0; cs1=u1; cs2=u2; cs3=u3; cs4=u4; cs5=u5;
            }

            // ---- per-lane start: A^(16*lane)*t + exclusive b ----
            float v0=t0,v1=t1,v2=t2, v3=t3,v4=t4,v5=t5;
            #pragma unroll
            for (int k = 0; k < 5; ++k) {
                if (lane & (1 << k)) {
                    const float* L0 = swL[0][k];
                    const float* L1 = swL[1][k];
                    float u0 = fmaf(L0[0],v0, fmaf(L0[1],v1, L0[2]*v2));
                    float u1 = fmaf(L0[3],v0, fmaf(L0[4],v1, L0[5]*v2));
                    float u2 = fmaf(L0[6],v0, fmaf(L0[7],v1, L0[8]*v2));
                    float u3 = fmaf(L1[0],v3, fmaf(L1[1],v4, L1[2]*v5));
                    float u4 = fmaf(L1[3],v3, fmaf(L1[4],v4, L1[5]*v5));
                    float u5 = fmaf(L1[6],v3, fmaf(L1[7],v4, L1[8]*v5));
                    v0=u0; v1=u1; v2=u2; v3=u3; v4=u4; v5=u5;
                }
            }
            float pb0 = __shfl_up_sync(0xffffffffu, b0, 1);
            float pb1 = __shfl_up_sync(0xffffffffu, b1, 1);
            float pb2 = __shfl_up_sync(0xffffffffu, b2, 1);
            float pb3 = __shfl_up_sync(0xffffffffu, b3, 1);
            float pb4 = __shfl_up_sync(0xffffffffu, b4, 1);
            float pb5 = __shfl_up_sync(0xffffffffu, b5, 1);
            float s0 = lane ? (v0 + pb0) : v0;
            float s1 = lane ? (v1 + pb1) : v1;
            float s2 = lane ? (v2 + pb2) : v2;
            float s3 = lane ? (v3 + pb3) : v3;
            float s4 = lane ? (v4 + pb4) : v4;
            float s5 = lane ? (v5 + pb5) : v5;

            // ---- phase C: re-run from true state; overwrite raw with x ----
            float2* wp = buf + tid * PITCH;
            #pragma unroll
            for (int j = 0; j < SEG; ++j) {
                float2 rn = wp[j];
                float e0 = fmaf(s0v, rn.x, k0);
                float e1 = fmaf(c10, rn.x, fmaf(c11, rn.y, k1));
                float x = fmaf(p2, s2, fmaf(p1, s1, fmaf(p0, s0, e0)));
                float y = fmaf(q2, s5, fmaf(q1, s4, fmaf(q0, s3, e1)));
                wp[j] = make_float2(x, y);
                s0 = s1; s1 = s2; s2 = x;
                s3 = s4; s4 = s5; s5 = y;
            }
        }
        __syncthreads();                      // S3

        // ---- phase D: coalesced float2 flush -> out (t = tbase + 3 + s) ----
        if (h < NTILES - 1) {
            #pragma unroll
            for (int k = 0; k < TILE / NTH; ++k) {
                const int s = tid + k * NTH;
                odst[tbase + 3 + s] = buf[(s >> 4) * PITCH + (s & 15)];
            }
        } else {
            const int nh = NNOISE - tbase;
            #pragma unroll
            for (int k = 0; k < TILE / NTH; ++k) {
                const int s = tid + k * NTH;
                if (s < nh)
                    odst[tbase + 3 + s] = buf[(s >> 4) * PITCH + (s & 15)];
            }
        }
        // no trailing barrier: next iteration's S1 separates D from buffer reuse
    }
}

extern "C" void kernel_launch(void* const* d_in, const int* in_sizes, int n_in,
                              void* d_out, int out_size)
{
    const float* alpha   = (const float*)d_in[0];
    const float* xmu     = (const float*)d_in[1];
    const float* sigma   = (const float*)d_in[2];
    const float* rho     = (const float*)d_in[3];
    const float* mu      = (const float*)d_in[4];
    const float* x_0     = (const float*)d_in[5];
    const float* normals = (const float*)d_in[6];
    float* out = (float*)d_out;

    arma_scan<<<TRIALS, NTH>>>(alpha, xmu, sigma, rho, mu, x_0, normals, out);
}

// round 15
// speedup vs baseline: 1.4240x; 1.3329x over previous
#include <cuda_runtime.h>
#include <cstdint>

// AR(3), 2 dims, diagonal alpha. 4096 trials x 8192 steps.
// One block per trial, 4 tiles of 2048 noise steps, SEG=16, dims fused.
// Double-buffered cp.async pipeline (identical to the 115.2us R11 kernel).
// Single change vs R11: per-lane prefix matrices A^(16*lane) are precomputed
// once per block into smem (swP), replacing the per-tile 5-level predicated
// binary-expansion loop with ONE mat-vec per scan thread.
//   B: 16 x LDS.64: zero-init dual-chain run -> 6-float offset b
//   scan: uniform-matrix affine scan (shuffle b only; per-dim A^(16*2^k))
//   chain: tid0 serial warp-total composition (A^512 uniform)
//   per-lane: v = swP[d][lane] * warp_start  (precomputed matrix)
//   C: re-run both chains from true states, in-place
//   D: coalesced float2 flush -> out
// Tail zero-filled via cp.async src-size=0 -> branchless fixed loops.

#define TRIALS 4096
#define STEPS  8192
#define NNOISE (STEPS - 3)     // 8189
#define TILE   2048
#define NTILES 4               // 3 x 2048 + 2045 (zero-padded)
#define SEG    16
#define NSEG   128
#define NTH    256
#define PITCH  17              // float2 per segment (16 + 1 pad): word stride 34
#define BUFSZ  (NSEG * PITCH)  // 2176 float2 per buffer

__device__ __forceinline__ void cp_async8(uint32_t dst, const void* src, int sz) {
    asm volatile("cp.async.ca.shared.global [%0], [%1], 8, %2;"
                 :: "r"(dst), "l"(src), "r"(sz));
}

__global__ __launch_bounds__(NTH, 5)
void arma_scan(const float* __restrict__ alpha, const float* __restrict__ xmu,
               const float* __restrict__ sigma, const float* __restrict__ rho_p,
               const float* __restrict__ mu,    const float* __restrict__ x_0,
               const float* __restrict__ normals, float* __restrict__ out)
{
    __shared__ float2 smv[2 * BUFSZ];        // 2 x 17408 B = 34.8 KB
    __shared__ float  swL[2][6][9];          // per-dim A^(16*2^k), k=0..5
    __shared__ float  swP[2][32][9];         // per-dim A^(16*lane), lane=0..31
    __shared__ float  swb[4][6];             // warp-total offsets
    __shared__ float  sst[4][6];             // warp start states

    const int tid  = threadIdx.x;
    const int lane = tid & 31;
    const int wd   = tid >> 5;
    const int tr   = blockIdx.x;

    // ---- parameters ----
    const float s0v = sigma[0], s1v = sigma[1];
    const float rho = rho_p[0];
    const float c10 = rho * s1v;
    const float c11 = sqrtf(1.0f - rho * rho) * s1v;
    const float k0  = mu[0] + xmu[0] * (1.0f - alpha[0] - alpha[2] - alpha[4]);
    const float k1  = mu[1] + xmu[1] * (1.0f - alpha[1] - alpha[3] - alpha[5]);
    const float p0 = alpha[0], p1 = alpha[2], p2 = alpha[4];   // dim 0
    const float q0 = alpha[1], q1 = alpha[3], q2 = alpha[5];   // dim 1

    const float2* nsrc = (const float2*)normals + (size_t)tr * NNOISE;
    float2*       odst = (float2*)out + (size_t)tr * STEPS;
    const uint32_t sbase = (uint32_t)__cvta_generic_to_shared(smv);

    // ---- preload tile 0 immediately (lands under init compute) ----
    {
        #pragma unroll
        for (int k = 0; k < TILE / NTH; ++k) {
            const int s = tid + k * NTH;
            cp_async8(sbase + (uint32_t)(((s >> 4) * PITCH + (s & 15)) * 8),
                      nsrc + s, 8);
        }
        asm volatile("cp.async.commit_group;");
    }

    // first ORDER outputs = x_0 verbatim
    if (tid < 6) out[(size_t)tr * STEPS * 2 + tid] = x_0[tr * 6 + tid];

    // ---- one-time: level matrices A^(16*2^k) for dim = tid (threads 0,1) ----
    if (tid < 2) {
        const float a0 = alpha[0 + tid], a1 = alpha[2 + tid], a2 = alpha[4 + tid];
        float m0=1,m1=0,m2=0, m3=0,m4=1,m5=0, m6=0,m7=0,m8=1;
        #pragma unroll
        for (int j = 0; j < SEG; ++j) {
            float r0 = fmaf(a0, m0, fmaf(a1, m3, a2 * m6));
            float r1 = fmaf(a0, m1, fmaf(a1, m4, a2 * m7));
            float r2 = fmaf(a0, m2, fmaf(a1, m5, a2 * m8));
            m0=m3; m1=m4; m2=m5;  m3=m6; m4=m7; m5=m8;  m6=r0; m7=r1; m8=r2;
        }
        float* L = swL[tid][0];
        L[0]=m0; L[1]=m1; L[2]=m2; L[3]=m3; L[4]=m4; L[5]=m5; L[6]=m6; L[7]=m7; L[8]=m8;
        #pragma unroll
        for (int k = 1; k < 6; ++k) {
            float c0 = fmaf(m0,m0, fmaf(m1,m3, m2*m6));
            float c1 = fmaf(m0,m1, fmaf(m1,m4, m2*m7));
            float c2 = fmaf(m0,m2, fmaf(m1,m5, m2*m8));
            float c3 = fmaf(m3,m0, fmaf(m4,m3, m5*m6));
            float c4 = fmaf(m3,m1, fmaf(m4,m4, m5*m7));
            float c5 = fmaf(m3,m2, fmaf(m4,m5, m5*m8));
            float c6 = fmaf(m6,m0, fmaf(m7,m3, m8*m6));
            float c7 = fmaf(m6,m1, fmaf(m7,m4, m8*m7));
            float c8 = fmaf(m6,m2, fmaf(m7,m5, m8*m8));
            m0=c0; m1=c1; m2=c2; m3=c3; m4=c4; m5=c5; m6=c6; m7=c7; m8=c8;
            float* Lk = swL[tid][k];
            Lk[0]=m0; Lk[1]=m1; Lk[2]=m2; Lk[3]=m3; Lk[4]=m4;
            Lk[5]=m5; Lk[6]=m6; Lk[7]=m7; Lk[8]=m8;
        }
    }
    __syncthreads();    // swL visible

    // ---- one-time: per-lane matrices A^(16*l) (threads 0..63) ----
    if (tid < 64) {
        const int d = tid >> 5, l = tid & 31;
        float m0=1,m1=0,m2=0, m3=0,m4=1,m5=0, m6=0,m7=0,m8=1;
        #pragma unroll
        for (int k = 0; k < 5; ++k) {
            if (l & (1 << k)) {
                const float* L = swL[d][k];
                // M <- L * M
                float c0 = fmaf(L[0],m0, fmaf(L[1],m3, L[2]*m6));
                float c1 = fmaf(L[0],m1, fmaf(L[1],m4, L[2]*m7));
                float c2 = fmaf(L[0],m2, fmaf(L[1],m5, L[2]*m8));
                float c3 = fmaf(L[3],m0, fmaf(L[4],m3, L[5]*m6));
                float c4 = fmaf(L[3],m1, fmaf(L[4],m4, L[5]*m7));
                float c5 = fmaf(L[3],m2, fmaf(L[4],m5, L[5]*m8));
                float c6 = fmaf(L[6],m0, fmaf(L[7],m3, L[8]*m6));
                float c7 = fmaf(L[6],m1, fmaf(L[7],m4, L[8]*m7));
                float c8 = fmaf(L[6],m2, fmaf(L[7],m5, L[8]*m8));
                m0=c0; m1=c1; m2=c2; m3=c3; m4=c4; m5=c5; m6=c6; m7=c7; m8=c8;
            }
        }
        float* P = swP[d][l];
        P[0]=m0; P[1]=m1; P[2]=m2; P[3]=m3; P[4]=m4; P[5]=m5; P[6]=m6; P[7]=m7; P[8]=m8;
    }

    // per-block serial carry (tid==0)
    float cs0=0.f, cs1=0.f, cs2=0.f, cs3=0.f, cs4=0.f, cs5=0.f;
    if (tid == 0) {
        cs0 = x_0[tr*6 + 0]; cs1 = x_0[tr*6 + 2]; cs2 = x_0[tr*6 + 4];  // d0
        cs3 = x_0[tr*6 + 1]; cs4 = x_0[tr*6 + 3]; cs5 = x_0[tr*6 + 5];  // d1
    }

    #pragma unroll
    for (int h = 0; h < NTILES; ++h) {
        const int tbase = h * TILE;
        float2* buf = smv + (h & 1) * BUFSZ;

        asm volatile("cp.async.wait_group 0;");
        __syncthreads();                      // S1: tile h resident for all

        // ---- issue next tile's async copy (overlaps B/scan/C/D) ----
        if (h + 1 < NTILES) {
            const int gbase = (h + 1) * TILE;
            const uint32_t dbase = sbase + (uint32_t)(((h + 1) & 1) * BUFSZ * 8);
            if (h + 1 < NTILES - 1) {
                #pragma unroll
                for (int k = 0; k < TILE / NTH; ++k) {
                    const int s = tid + k * NTH;
                    cp_async8(dbase + (uint32_t)(((s >> 4) * PITCH + (s & 15)) * 8),
                              nsrc + gbase + s, 8);
                }
            } else {
                const int nh = NNOISE - gbase;            // 2045
                #pragma unroll
                for (int k = 0; k < TILE / NTH; ++k) {
                    const int s = tid + k * NTH;
                    const bool ok = s < nh;
                    cp_async8(dbase + (uint32_t)(((s >> 4) * PITCH + (s & 15)) * 8),
                              ok ? (nsrc + gbase + s) : nsrc, ok ? 8 : 0);
                }
            }
            asm volatile("cp.async.commit_group;");
        }

        // ---- phase B: zero-init dual-chain run on raw noise ----
        float b0=0.f,b1=0.f,b2=0.f, b3=0.f,b4=0.f,b5=0.f;
        if (tid < 128) {
            const float2* np = buf + tid * PITCH;
            #pragma unroll
            for (int j = 0; j < SEG; ++j) {
                float2 rn = np[j];
                float e0 = fmaf(s0v, rn.x, k0);
                float e1 = fmaf(c10, rn.x, fmaf(c11, rn.y, k1));
                float x = fmaf(p2, b2, fmaf(p1, b1, fmaf(p0, b0, e0)));
                float y = fmaf(q2, b5, fmaf(q1, b4, fmaf(q0, b3, e1)));
                b0 = b1; b1 = b2; b2 = x;
                b3 = b4; b4 = b5; b5 = y;
            }

            // ---- uniform-matrix inclusive b-scan ----
            #pragma unroll
            for (int k = 0; k < 5; ++k) {
                const int sh = 1 << k;
                float pb0 = __shfl_up_sync(0xffffffffu, b0, sh);
                float pb1 = __shfl_up_sync(0xffffffffu, b1, sh);
                float pb2 = __shfl_up_sync(0xffffffffu, b2, sh);
                float pb3 = __shfl_up_sync(0xffffffffu, b3, sh);
                float pb4 = __shfl_up_sync(0xffffffffu, b4, sh);
                float pb5 = __shfl_up_sync(0xffffffffu, b5, sh);
                if (lane >= sh) {
                    const float* L0 = swL[0][k];
                    const float* L1 = swL[1][k];
                    b0 = fmaf(L0[0], pb0, fmaf(L0[1], pb1, fmaf(L0[2], pb2, b0)));
                    b1 = fmaf(L0[3], pb0, fmaf(L0[4], pb1, fmaf(L0[5], pb2, b1)));
                    b2 = fmaf(L0[6], pb0, fmaf(L0[7], pb1, fmaf(L0[8], pb2, b2)));
                    b3 = fmaf(L1[0], pb3, fmaf(L1[1], pb4, fmaf(L1[2], pb5, b3)));
                    b4 = fmaf(L1[3], pb3, fmaf(L1[4], pb4, fmaf(L1[5], pb5, b4)));
                    b5 = fmaf(L1[6], pb3, fmaf(L1[7], pb4, fmaf(L1[8], pb5, b5)));
                }
            }
            if (lane == 31) {
                float* bw = swb[wd];
                bw[0]=b0; bw[1]=b1; bw[2]=b2; bw[3]=b3; bw[4]=b4; bw[5]=b5;
            }
        }
        __syncthreads();                      // S2

        // ---- serial warp-total chain (tid==0, A^512 per dim) ----
        if (tid == 0) {
            const float* L50 = swL[0][5];
            const float* L51 = swL[1][5];
            float t0=cs0,t1=cs1,t2=cs2, t3=cs3,t4=cs4,t5=cs5;
            #pragma unroll
            for (int w = 0; w < 4; ++w) {
                float* st = sst[w];
                st[0]=t0; st[1]=t1; st[2]=t2; st[3]=t3; st[4]=t4; st[5]=t5;
                const float* bw = swb[w];
                float u0 = fmaf(L50[0],t0, fmaf(L50[1],t1, fmaf(L50[2],t2, bw[0])));
                float u1 = fmaf(L50[3],t0, fmaf(L50[4],t1, fmaf(L50[5],t2, bw[1])));
                float u2 = fmaf(L50[6],t0, fmaf(L50[7],t1, fmaf(L50[8],t2, bw[2])));
                float u3 = fmaf(L51[0],t3, fmaf(L51[1],t4, fmaf(L51[2],t5, bw[3])));
                float u4 = fmaf(L51[3],t3, fmaf(L51[4],t4, fmaf(L51[5],t5, bw[4])));
                float u5 = fmaf(L51[6],t3, fmaf(L51[7],t4, fmaf(L51[8],t5, bw[5])));
                t0=u0; t1=u1; t2=u2; t3=u3; t4=u4; t5=u5;
            }
            cs0=t0; cs1=t1; cs2=t2; cs3=t3; cs4=t4; cs5=t5;   // carry
        }
        __syncthreads();                      // S3

        if (tid < 128) {
            // ---- per-lane start: single precomputed mat-vec + exclusive b ----
            const float* st = sst[wd];
            const float w0 = st[0], w1 = st[1], w2 = st[2];
            const float w3 = st[3], w4 = st[4], w5 = st[5];
            const float* P0 = swP[0][lane];
            const float* P1 = swP[1][lane];
            float v0 = fmaf(P0[0],w0, fmaf(P0[1],w1, P0[2]*w2));
            float v1 = fmaf(P0[3],w0, fmaf(P0[4],w1, P0[5]*w2));
            float v2 = fmaf(P0[6],w0, fmaf(P0[7],w1, P0[8]*w2));
            float v3 = fmaf(P1[0],w3, fmaf(P1[1],w4, P1[2]*w5));
            float v4 = fmaf(P1[3],w3, fmaf(P1[4],w4, P1[5]*w5));
            float v5 = fmaf(P1[6],w3, fmaf(P1[7],w4, P1[8]*w5));

            float pb0 = __shfl_up_sync(0xffffffffu, b0, 1);
            float pb1 = __shfl_up_sync(0xffffffffu, b1, 1);
            float pb2 = __shfl_up_sync(0xffffffffu, b2, 1);
            float pb3 = __shfl_up_sync(0xffffffffu, b3, 1);
            float pb4 = __shfl_up_sync(0xffffffffu, b4, 1);
            float pb5 = __shfl_up_sync(0xffffffffu, b5, 1);
            float s0 = lane ? (v0 + pb0) : v0;
            float s1 = lane ? (v1 + pb1) : v1;
            float s2 = lane ? (v2 + pb2) : v2;
            float s3 = lane ? (v3 + pb3) : v3;
            float s4 = lane ? (v4 + pb4) : v4;
            float s5 = lane ? (v5 + pb5) : v5;

            // ---- phase C: re-run from true state; overwrite raw with x ----
            float2* wp = buf + tid * PITCH;
            #pragma unroll
            for (int j = 0; j < SEG; ++j) {
                float2 rn = wp[j];
                float e0 = fmaf(s0v, rn.x, k0);
                float e1 = fmaf(c10, rn.x, fmaf(c11, rn.y, k1));
                float x = fmaf(p2, s2, fmaf(p1, s1, fmaf(p0, s0, e0)));
                float y = fmaf(q2, s5, fmaf(q1, s4, fmaf(q0, s3, e1)));
                wp[j] = make_float2(x, y);
                s0 = s1; s1 = s2; s2 = x;
                s3 = s4; s4 = s5; s5 = y;
            }
        }
        __syncthreads();                      // S4

        // ---- phase D: coalesced float2 flush -> out (t = tbase + 3 + s) ----
        if (h < NTILES - 1) {
            #pragma unroll
            for (int k = 0; k < TILE / NTH; ++k) {
                const int s = tid + k * NTH;
                odst[tbase + 3 + s] = buf[(s >> 4) * PITCH + (s & 15)];
            }
        } else {
            const int nh = NNOISE - tbase;
            #pragma unroll
            for (int k = 0; k < TILE / NTH; ++k) {
                const int s = tid + k * NTH;
                if (s < nh)
                    odst[tbase + 3 + s] = buf[(s >> 4) * PITCH + (s & 15)];
            }
        }
        // no trailing barrier: next iteration's S1 separates D from buffer reuse
    }
}

extern "C" void kernel_launch(void* const* d_in, const int* in_sizes, int n_in,
                              void* d_out, int out_size)
{
    const float* alpha   = (const float*)d_in[0];
    const float* xmu     = (const float*)d_in[1];
    const float* sigma   = (const float*)d_in[2];
    const float* rho     = (const float*)d_in[3];
    const float* mu      = (const float*)d_in[4];
    const float* x_0     = (const float*)d_in[5];
    const float* normals = (const float*)d_in[6];
    float* out = (float*)d_out;

    arma_scan<<<TRIALS, NTH>>>(alpha, xmu, sigma, rho, mu, x_0, normals, out);
}